// round 6
// baseline (speedup 1.0000x reference)
#include <cuda_runtime.h>

#define B_   8
#define C_   256
#define CC_  64
#define H_   64
#define W_   64
#define HW_  4096
#define OE_  36
#define EPSF 1e-5f

typedef unsigned long long u64;

__device__ __forceinline__ u64 pk2(float lo, float hi) {
    u64 r; asm("mov.b64 %0, {%1,%2};" : "=l"(r) : "f"(lo), "f"(hi)); return r;
}
__device__ __forceinline__ u64 splat2(float v) { return pk2(v, v); }
__device__ __forceinline__ void fma2(u64& d, u64 a, u64 b) {
    asm("fma.rn.f32x2 %0, %1, %2, %0;" : "+l"(d) : "l"(a), "l"(b));
}
__device__ __forceinline__ u64 add2(u64 a, u64 b) {
    u64 r; asm("add.rn.f32x2 %0, %1, %2;" : "=l"(r) : "l"(a), "l"(b)); return r;
}
__device__ __forceinline__ float2 up2(u64 v) {
    float2 f; asm("mov.b64 {%0,%1}, %2;" : "=f"(f.x), "=f"(f.y) : "l"(v)); return f;
}

// ---------------- scratch ----------------
__device__ float g_comp[B_ * CC_ * HW_];
__device__ float g_enc [B_ * OE_ * HW_];
__device__ float g_scale[CC_];
__device__ float g_shift[CC_];
__device__ float g_part[CC_][4][2];
// w2 transposed + padded: [(c*9+ij)*48 + (o/6)*8 + o%6]
__device__ float g_wt[CC_ * 9 * 48];

// ---------------- K0: transpose+pad w2 once ----------------
__global__ __launch_bounds__(256) void k0_wt(const float* __restrict__ w2)
{
    int idx = blockIdx.x * 256 + threadIdx.x;
    if (idx >= CC_ * 9 * OE_) return;
    int o = idx % 36;
    int t = idx / 36;
    int ij = t % 9, c = t / 9;
    g_wt[t * 48 + (o / 6) * 8 + (o % 6)] = w2[(o * CC_ + c) * 9 + ij];
}

// ---------------- K1: 1x1 conv GEMM, 512 thr = 8 og x 2 kc-halves ----------------
__global__ __launch_bounds__(512) void k1_compress(
    const float* __restrict__ x, const float* __restrict__ w1,
    const float* __restrict__ b1)
{
    __shared__ __align__(16) float blob[16 * 128 + 16 * 64 * 2];  // sx | swd
    float (*sx)[128] = (float(*)[128])blob;
    u64 (*swd)[64] = (u64(*)[64])(blob + 16 * 128);

    int b   = blockIdx.x >> 5;
    int hw0 = (blockIdx.x & 31) * 128;
    int tid = threadIdx.x;
    int warp = tid >> 5;
    int og   = warp & 7;           // warp-uniform
    int half = warp >> 3;          // 0/1: kc 0-7 or 8-15
    int hg   = tid & 31;

    u64 acc[8][2];
#pragma unroll
    for (int i = 0; i < 8; i++) { acc[i][0] = 0ull; acc[i][1] = 0ull; }

    const float* xb = x + (size_t)b * C_ * HW_ + hw0;
    for (int cb = 0; cb < C_; cb += 16) {
        {
            int kc = tid >> 5, hl = tid & 31;
            ((float4*)sx[kc])[hl] = ((const float4*)(xb + (size_t)(cb + kc) * HW_))[hl];
        }
#pragma unroll
        for (int k = 0; k < 2; k++) {
            int q = tid + k * 512;
            int kc = q >> 6, o = q & 63;
            swd[kc][o] = splat2(w1[o * C_ + cb + kc]);
        }
        __syncthreads();
#pragma unroll
        for (int kc = 0; kc < 8; kc++) {
            int kcg = half * 8 + kc;
            ulonglong2 xv = *(const ulonglong2*)&sx[kcg][hg * 4];
#pragma unroll
            for (int k = 0; k < 4; k++) {
                ulonglong2 wp = *(const ulonglong2*)&swd[kcg][og * 8 + 2 * k];
                fma2(acc[2 * k][0],     wp.x, xv.x);
                fma2(acc[2 * k][1],     wp.x, xv.y);
                fma2(acc[2 * k + 1][0], wp.y, xv.x);
                fma2(acc[2 * k + 1][1], wp.y, xv.y);
            }
        }
        __syncthreads();
    }
    // combine halves: two passes of 8 u64 through the 16KB smem blob
    u64* red = (u64*)blob;
#pragma unroll
    for (int pass = 0; pass < 2; pass++) {
        if (half == 1) {
            u64* dst = red + (size_t)(tid - 256) * 8;
#pragma unroll
            for (int i = 0; i < 4; i++) {
                dst[2 * i]     = acc[pass * 4 + i][0];
                dst[2 * i + 1] = acc[pass * 4 + i][1];
            }
        }
        __syncthreads();
        if (half == 0) {
            const u64* src = red + (size_t)tid * 8;
#pragma unroll
            for (int i = 0; i < 4; i++) {
                acc[pass * 4 + i][0] = add2(acc[pass * 4 + i][0], src[2 * i]);
                acc[pass * 4 + i][1] = add2(acc[pass * 4 + i][1], src[2 * i + 1]);
            }
        }
        __syncthreads();
    }
    if (half == 0) {
#pragma unroll
        for (int oo = 0; oo < 8; oo++) {
            int o = og * 8 + oo;
            float bias = b1[o];
            float2 lo = up2(acc[oo][0]), hi = up2(acc[oo][1]);
            float4 r = {lo.x + bias, lo.y + bias, hi.x + bias, hi.y + bias};
            *(float4*)&g_comp[((size_t)b * CC_ + o) * HW_ + hw0 + hg * 4] = r;
        }
    }
}

// ---------------- K2a: partial batch stats (256 blocks) ----------------
__global__ __launch_bounds__(256) void k2a_stats()
{
    __shared__ float ss[256], sq[256];
    int o = blockIdx.x >> 2, q = blockIdx.x & 3;
    int tid = threadIdx.x;
    float s = 0.f, qq = 0.f;
#pragma unroll
    for (int bb = 0; bb < 2; bb++) {
        int b = q * 2 + bb;
        const float4* base = (const float4*)&g_comp[((size_t)b * CC_ + o) * HW_];
#pragma unroll
        for (int k = 0; k < 4; k++) {
            float4 v = base[tid + k * 256];
            s  += v.x + v.y + v.z + v.w;
            qq += v.x * v.x + v.y * v.y + v.z * v.z + v.w * v.w;
        }
    }
    ss[tid] = s; sq[tid] = qq;
    __syncthreads();
    for (int st = 128; st > 0; st >>= 1) {
        if (tid < st) { ss[tid] += ss[tid + st]; sq[tid] += sq[tid + st]; }
        __syncthreads();
    }
    if (tid == 0) { g_part[o][q][0] = ss[0]; g_part[o][q][1] = sq[0]; }
}

// ---------------- K2b: combine -> BN scale/shift ----------------
__global__ __launch_bounds__(64) void k2b_stats(
    const float* __restrict__ gamma, const float* __restrict__ beta)
{
    int o = threadIdx.x;
    float s = g_part[o][0][0] + g_part[o][1][0] + g_part[o][2][0] + g_part[o][3][0];
    float q = g_part[o][0][1] + g_part[o][1][1] + g_part[o][2][1] + g_part[o][3][1];
    float n = (float)(B_ * HW_);
    float mean = s / n;
    float var  = q / n - mean * mean;
    float sc   = gamma[o] * rsqrtf(var + EPSF);
    g_scale[o] = sc;
    g_shift[o] = beta[o] - mean * sc;
}

// ---------------- K3: 3x3 conv 64->36, 384 thr = 6 og x 2 ci-halves ----------------
// grid (4,8,8): tile 16w x 8h. lane: py=lane>>2, px0=(lane&3)*4.
// xs transposed [ci][col][row] -> conflict-free scalar LDS.
__global__ __launch_bounds__(384) void k3_conv(const float* __restrict__ b2)
{
    __shared__ __align__(16) float xs[16][18][10];   // 2880 floats
    __shared__ __align__(16) float ws[16 * 9 * 48];  // 6912 floats
    __shared__ float ssc[64], ssh[64];
    int w0 = blockIdx.x * 16, h0 = blockIdx.y * 8, b = blockIdx.z;
    int tid = threadIdx.x;
    if (tid < 64) { ssc[tid] = g_scale[tid]; ssh[tid] = g_shift[tid]; }
    int warp = tid >> 5;
    int og   = warp % 6;           // warp-uniform
    int half = warp / 6;           // 0/1: ci 0-7 or 8-15 of each chunk
    int lane = tid & 31;
    int py   = lane >> 2;
    int px0  = (lane & 3) * 4;

    u64 acc[3][4];
#pragma unroll
    for (int op = 0; op < 3; op++)
#pragma unroll
        for (int p = 0; p < 4; p++) acc[op][p] = 0ull;

    const float* compb = g_comp + (size_t)b * CC_ * HW_;
    for (int cb = 0; cb < 64; cb += 16) {
        __syncthreads();
        for (int idx = tid; idx < 2880; idx += 384) {      // 16ci * 10row * 18col
            int ci = idx / 180; int rem = idx - ci * 180;
            int row = rem / 18; int col = rem - row * 18;
            int gy = h0 + row - 1, gx = w0 + col - 1;
            float v = 0.f;
            if (gy >= 0 && gy < 64 && gx >= 0 && gx < 64) {
                float raw = compb[(cb + ci) * HW_ + gy * 64 + gx];
                v = fmaxf(raw * ssc[cb + ci] + ssh[cb + ci], 0.f);
            }
            xs[ci][col][row] = v;
        }
        {   // 16ci of padded weights: 6912 words = 1728 float4
            const float4* src = (const float4*)(g_wt + cb * 432);
            for (int idx = tid; idx < 1728; idx += 384)
                ((float4*)ws)[idx] = src[idx];
        }
        __syncthreads();
#pragma unroll
        for (int ci = 0; ci < 8; ci++) {
            int cl = half * 8 + ci;
            u64 s[3][6];
#pragma unroll
            for (int k = 0; k < 6; k++)
#pragma unroll
                for (int r = 0; r < 3; r++)
                    s[r][k] = splat2(xs[cl][px0 + k][py + r]);
            const float* wci = ws + cl * 432 + og * 8;
#pragma unroll
            for (int ij = 0; ij < 9; ij++) {
                int i = ij / 3, j = ij % 3;
                ulonglong2 wab = *(const ulonglong2*)(wci + ij * 48);
                u64 wc = *(const u64*)(wci + ij * 48 + 4);
#pragma unroll
                for (int p = 0; p < 4; p++) {
                    fma2(acc[0][p], s[i][j + p], wab.x);
                    fma2(acc[1][p], s[i][j + p], wab.y);
                    fma2(acc[2][p], s[i][j + p], wc);
                }
            }
        }
    }
    // combine ci-halves through ws (3456 u64 >= 192*12)
    u64* red = (u64*)ws;
    __syncthreads();
    if (half == 1) {
        u64* dst = red + (size_t)(tid - 192) * 12;
#pragma unroll
        for (int op = 0; op < 3; op++)
#pragma unroll
            for (int p = 0; p < 4; p++) dst[op * 4 + p] = acc[op][p];
    }
    __syncthreads();
    if (half == 0) {
        const u64* src = red + (size_t)tid * 12;
#pragma unroll
        for (int op = 0; op < 3; op++) {
            int o = og * 6 + 2 * op;
            float bia0 = b2[o], bia1 = b2[o + 1];
            float* e0 = g_enc + ((size_t)b * OE_ + o) * HW_ + (h0 + py) * 64 + w0 + px0;
            float* e1 = e0 + HW_;
#pragma unroll
            for (int p = 0; p < 4; p++) {
                float2 r = up2(add2(acc[op][p], src[op * 4 + p]));
                e0[p] = r.x + bia0;
                e1[p] = r.y + bia1;
            }
        }
    }
}

// ---------------- K4: softmax over H, block per (b,ch) ----------------
__global__ __launch_bounds__(256) void k4_softmax()
{
    __shared__ float red[4][64];
    int b = blockIdx.x / 36, ch = blockIdx.x % 36;
    int tid = threadIdx.x;
    int w = tid & 63, hq = tid >> 6;
    float* base = g_enc + ((size_t)b * 36 + ch) * HW_;
    float v[16];
    float m = -1e30f;
#pragma unroll
    for (int i = 0; i < 16; i++) {
        v[i] = base[(hq * 16 + i) * 64 + w];
        m = fmaxf(m, v[i]);
    }
    red[hq][w] = m;
    __syncthreads();
    m = fmaxf(fmaxf(red[0][w], red[1][w]), fmaxf(red[2][w], red[3][w]));
    float s = 0.f;
#pragma unroll
    for (int i = 0; i < 16; i++) { v[i] = __expf(v[i] - m); s += v[i]; }
    __syncthreads();
    red[hq][w] = s;
    __syncthreads();
    float inv = 1.f / (red[0][w] + red[1][w] + red[2][w] + red[3][w]);
#pragma unroll
    for (int i = 0; i < 16; i++) base[(hq * 16 + i) * 64 + w] = v[i] * inv;
}

// ---------------- K5: CARAFE reassembly, f32x2 over w-pairs, STG.64 ----------------
__global__ __launch_bounds__(256) void k5_carafe(
    const float* __restrict__ x, float* __restrict__ out)
{
    __shared__ __align__(16) float xs[3][32][64];
    int h = blockIdx.x, b = blockIdx.y;
    int tid = threadIdx.x;
    int wt2 = tid & 31, cg = tid >> 5;
    int w0 = 2 * wt2;

    u64 kr2[4][9];
    const float* encb = g_enc + (size_t)b * 36 * HW_ + h * 64 + w0;
#pragma unroll
    for (int s = 0; s < 4; s++)
#pragma unroll
        for (int k = 0; k < 9; k++)
            kr2[s][k] = *(const u64*)(encb + (size_t)(s * 9 + k) * HW_);

    int hr0 = h > 0 ? h - 1 : 0;
    int hr2 = h < 63 ? h + 1 : 63;
    int hrow[3] = {hr0, h, hr2};
    int cm1 = w0 > 0 ? w0 - 1 : 0;
    int cp2 = w0 + 2 < 64 ? w0 + 2 : 63;
    float* outb = out + (size_t)b * C_ * 128 * 128;

    for (int cb = 0; cb < 256; cb += 32) {
        __syncthreads();
#pragma unroll
        for (int k = 0; k < 6; k++) {
            int q = tid + k * 256;
            int dr = q / 512;
            int cl = (q >> 4) & 31;
            int wq = q & 15;
            ((float4*)xs)[q] =
                ((const float4*)(x + (((size_t)b * C_ + cb + cl) * 64 + hrow[dr]) * 64))[wq];
        }
        __syncthreads();
#pragma unroll
        for (int cc = 0; cc < 4; cc++) {
            int cl = cg * 4 + cc;
            u64 p[3][3];
#pragma unroll
            for (int r = 0; r < 3; r++) {
                const float* row = &xs[r][cl][0];
                float  a = row[cm1];
                u64    mid = *(const u64*)&row[w0];
                float  d = row[cp2];
                float2 mf = up2(mid);
                p[r][0] = pk2(a, mf.x);
                p[r][1] = mid;
                p[r][2] = pk2(mf.y, d);
            }
            u64 acc[4] = {0ull, 0ull, 0ull, 0ull};
#pragma unroll
            for (int k2 = 0; k2 < 9; k2++) {
                int i = k2 / 3, j = k2 % 3;
                fma2(acc[0], p[i][j], kr2[0][k2]);
                fma2(acc[1], p[i][j], kr2[1][k2]);
                fma2(acc[2], p[i][j], kr2[2][k2]);
                fma2(acc[3], p[i][j], kr2[3][k2]);
            }
            int c = cb + cl;
            int s4 = c & 3;
            int row_o = 2 * h + (s4 >> 1);
            int colb = ((s4 & 1) << 6) + w0;
            int c4b = c >> 2;
#pragma unroll
            for (int s = 0; s < 4; s++)
                *(u64*)&outb[(((size_t)(s * 64 + c4b)) * 128 + row_o) * 128 + colb] = acc[s];
        }
    }
}

// ---------------- launch ----------------
extern "C" void kernel_launch(void* const* d_in, const int* in_sizes, int n_in,
                              void* d_out, int out_size)
{
    const float* x     = (const float*)d_in[0];
    const float* w1    = (const float*)d_in[1];
    const float* b1    = (const float*)d_in[2];
    const float* gamma = (const float*)d_in[3];
    const float* beta  = (const float*)d_in[4];
    const float* w2    = (const float*)d_in[5];
    const float* b2    = (const float*)d_in[6];
    float* out = (float*)d_out;

    k0_wt<<<81, 256>>>(w2);
    k1_compress<<<256, 512>>>(x, w1, b1);
    k2a_stats<<<256, 256>>>();
    k2b_stats<<<1, 64>>>(gamma, beta);
    k3_conv<<<dim3(4, 8, 8), 384>>>(b2);
    k4_softmax<<<288, 256>>>();
    k5_carafe<<<dim3(64, 8), 256>>>(x, out);
}